// round 6
// baseline (speedup 1.0000x reference)
#include <cuda_runtime.h>

// H_13048110646034 v6: persistent warps, single wave.
// Grid 1024 CTAs x 64 thr; each warp handles TWO p's (p, p+2048) back-to-back.
// cp.async weight ring (2 bufs x 4 i-rows x 4 mats); the fill slots at the end
// of p0's chunk loop prefetch p1's first chunks -> pipeline never drains.

#define B_  8
#define N_  16384
#define P_  4096

__device__ __forceinline__ void cp_async16(void* smem_dst, const void* gsrc) {
    unsigned saddr = (unsigned)__cvta_generic_to_shared(smem_dst);
    asm volatile("cp.async.cg.shared.global [%0], [%1], 16;\n" :: "r"(saddr), "l"(gsrc));
}
__device__ __forceinline__ void cp_commit() { asm volatile("cp.async.commit_group;\n"); }
template <int N>
__device__ __forceinline__ void cp_wait() {
    asm volatile("cp.async.wait_group %0;\n" :: "n"(N));
}

__global__ __launch_bounds__(64, 9)
void butterfly_local_v6(const float* __restrict__ x,
                        const float* __restrict__ Wrr,
                        const float* __restrict__ Wri,
                        const float* __restrict__ Wir,
                        const float* __restrict__ Wii,
                        const int*   __restrict__ perm,
                        float* __restrict__ out)
{
    const int w    = threadIdx.x >> 5;       // warp 0..1
    const int lane = threadIdx.x & 31;
    const int p0   = blockIdx.x * 2 + w;
    const int p1   = p0 + 2048;

    // Weights: [warp][buf][mat][i_local 4][o 64] = 16 KB total (8 KB/warp)
    __shared__ float Wsm[2][2][4][4][64];
    // x: [warp][i 64][cb 16] = 8 KB
    __shared__ float xsm[2][64][16];

    const float* const Wm[4] = { Wrr, Wri, Wir, Wii };
    const size_t pq[2] = { (size_t)p0 * 1024, (size_t)p1 * 1024 };

    // fill chunk _c (i in [_c*4,_c*4+4)) of p with float4-base PQ into BUF
    #define FILL_CHUNK(PQ, CC, BUF)                                           \
        {                                                                     \
            const size_t _pq = (PQ);                                          \
            const int _c = (CC);                                              \
            _Pragma("unroll")                                                 \
            for (int k = 0; k < 8; k++) {                                     \
                const int mat = k >> 1;                                       \
                const int rem = (k & 1) * 32 + lane;                          \
                cp_async16(((float4*)&Wsm[w][BUF][mat][0][0]) + rem,          \
                           ((const float4*)Wm[mat]) + _pq + _c * 64 + rem);   \
            }                                                                 \
            cp_commit();                                                      \
        }

    // gather x for block P into xsm[w]
    #define GATHER_X(P)                                                       \
        {                                                                     \
            const int _p = (P);                                               \
            const int cb = lane & 15;                                         \
            const int hi = lane >> 4;                                         \
            _Pragma("unroll")                                                 \
            for (int it = 0; it < 8; it++) {                                  \
                const int jf = it * 2 + hi;                                   \
                const int j  = jf >> 2;                                       \
                const int f4 = jf & 3;                                        \
                const int n  = __ldg(&perm[_p * 4 + j]);                      \
                const float4 v = *(const float4*)&x[(((size_t)cb * N_) + n) * 16 + f4 * 4]; \
                const int i0 = j * 16 + f4 * 4;                               \
                xsm[w][i0 + 0][cb] = v.x;                                     \
                xsm[w][i0 + 1][cb] = v.y;                                     \
                xsm[w][i0 + 2][cb] = v.z;                                     \
                xsm[w][i0 + 3][cb] = v.w;                                     \
            }                                                                 \
        }

    FILL_CHUNK(pq[0], 0, 0);
    FILL_CHUNK(pq[0], 1, 1);
    GATHER_X(p0);
    __syncwarp();

    const int oslot = lane & 7;
    const int bslot = (lane >> 3) & 1;
    const int cout  = lane >> 4;
    const int matA  = cout * 2;
    const int matB  = cout * 2 + 1;

    for (int rep = 0; rep < 2; rep++) {
        const int p = rep ? p1 : p0;

        if (rep) {                            // seam: p1 weights already in flight
            GATHER_X(p1);
            __syncwarp();
        }

        float4 accLo[4], accHi[4];
        #pragma unroll
        for (int k = 0; k < 4; k++) {
            accLo[k] = make_float4(0.f, 0.f, 0.f, 0.f);
            accHi[k] = make_float4(0.f, 0.f, 0.f, 0.f);
        }

        for (int c = 0; c < 16; c++) {
            cp_wait<1>();
            __syncwarp();
            const int buf = c & 1;

            #pragma unroll
            for (int ii = 0; ii < 4; ii++) {
                const int i = c * 4 + ii;
                const float4 xa  = *(const float4*)&xsm[w][i][bslot * 8];
                const float4 xb  = *(const float4*)&xsm[w][i][bslot * 8 + 4];
                const float4 wA0 = *(const float4*)&Wsm[w][buf][matA][ii][oslot * 4];
                const float4 wA1 = *(const float4*)&Wsm[w][buf][matA][ii][32 + oslot * 4];
                const float4 wB0 = *(const float4*)&Wsm[w][buf][matB][ii][oslot * 4];
                const float4 wB1 = *(const float4*)&Wsm[w][buf][matB][ii][32 + oslot * 4];

                const float xr[4] = { xa.x, xa.z, xb.x, xb.z };
                const float xi[4] = { xa.y, xa.w, xb.y, xb.w };

                #pragma unroll
                for (int k = 0; k < 4; k++) {
                    accLo[k].x = fmaf(xr[k], wA0.x, accLo[k].x); accLo[k].x = fmaf(xi[k], wB0.x, accLo[k].x);
                    accLo[k].y = fmaf(xr[k], wA0.y, accLo[k].y); accLo[k].y = fmaf(xi[k], wB0.y, accLo[k].y);
                    accLo[k].z = fmaf(xr[k], wA0.z, accLo[k].z); accLo[k].z = fmaf(xi[k], wB0.z, accLo[k].z);
                    accLo[k].w = fmaf(xr[k], wA0.w, accLo[k].w); accLo[k].w = fmaf(xi[k], wB0.w, accLo[k].w);
                    accHi[k].x = fmaf(xr[k], wA1.x, accHi[k].x); accHi[k].x = fmaf(xi[k], wB1.x, accHi[k].x);
                    accHi[k].y = fmaf(xr[k], wA1.y, accHi[k].y); accHi[k].y = fmaf(xi[k], wB1.y, accHi[k].y);
                    accHi[k].z = fmaf(xr[k], wA1.z, accHi[k].z); accHi[k].z = fmaf(xi[k], wB1.z, accHi[k].z);
                    accHi[k].w = fmaf(xr[k], wA1.w, accHi[k].w); accHi[k].w = fmaf(xi[k], wB1.w, accHi[k].w);
                }
            }

            __syncwarp();                     // all lanes done reading buf
            const int g = rep * 16 + c + 2;   // global chunk to fill next
            if (g < 32) {
                FILL_CHUNK(pq[g >> 4], g & 15, buf);
            } else {
                cp_commit();                  // keep group accounting uniform
            }
        }

        // store: out[b, cout, 4p..4p+3, :] = contiguous 64-float run
        #pragma unroll
        for (int k = 0; k < 4; k++) {
            const int b = bslot * 4 + k;
            const size_t off = (((size_t)(b * 2 + cout) * N_) + 4 * (size_t)p) * 16;
            *(float4*)&out[off + oslot * 4]      = accLo[k];
            *(float4*)&out[off + 32 + oslot * 4] = accHi[k];
        }
    }
    #undef FILL_CHUNK
    #undef GATHER_X
}

extern "C" void kernel_launch(void* const* d_in, const int* in_sizes, int n_in,
                              void* d_out, int out_size)
{
    const float* x    = (const float*)d_in[0];
    const float* Wrr  = (const float*)d_in[1];
    const float* Wri  = (const float*)d_in[2];
    const float* Wir  = (const float*)d_in[3];
    const float* Wii  = (const float*)d_in[4];
    const int*   perm = (const int*)d_in[5];
    float* out = (float*)d_out;

    butterfly_local_v6<<<P_ / 4, 64>>>(x, Wrr, Wri, Wir, Wii, perm, out);
}